// round 1
// baseline (speedup 1.0000x reference)
#include <cuda_runtime.h>
#include <math.h>

#define NPIX 4096
#define CDIM 256
#define NLOW 256
#define KLEN 32
#define NHEADS 8
#define HD 32
#define BATCH 2

// ---------------- scratch (no allocations allowed) ----------------
__device__ float g_q[BATCH * NPIX * CDIM];   // (B, N, C)
__device__ float g_k[BATCH * NPIX * CDIM];
__device__ float g_v[BATCH * NPIX * CDIM];
__device__ float g_x[BATCH * NPIX * CDIM];
__device__ int   g_idx[BATCH * NLOW * KLEN];

// ---------------- top-2 + index expansion ----------------
// one thread per (b, low-res query row); scans 256 coarse scores
__global__ void topk_expand_kernel(const float* __restrict__ cmap,
                                   int* __restrict__ idx) {
    int b = blockIdx.x;
    int i = threadIdx.x;                       // 0..255
    const float* row = cmap + ((size_t)b * NLOW + i) * NLOW;
    float m1 = -1e30f, m2 = -1e30f;
    int i1 = 0, i2 = 0;
    for (int j = 0; j < NLOW; j++) {
        float v = row[j];
        if (v > m1)      { m2 = m1; i2 = i1; m1 = v; i1 = j; }
        else if (v > m2) { m2 = v;  i2 = j; }
    }
    int tk0 = i1, tk1 = i2;
    int* orow = idx + ((size_t)b * NLOW + i) * KLEN;
    #pragma unroll
    for (int k = 0; k < 2; k++) {
        int t  = (k == 0) ? tk0 : tk1;
        int r0 = (t >> 4) << 2;   // (t / W_low) * RATIO, W_low=16
        int c0 = (t & 15) << 2;   // (t % W_low) * RATIO
        #pragma unroll
        for (int dr = 0; dr < 4; dr++)
            #pragma unroll
            for (int dc = 0; dc < 4; dc++)
                orow[k * 16 + dr * 4 + dc] = (r0 + dr) * 64 + (c0 + dc);
    }
}

// ---------------- projection GEMM: out[b,n,co] = sum_c A[b,c,n]*W[c,co]+bias ----------------
// A is (B, C, NPIX) (n contiguous), out is (B, NPIX, C) (c contiguous)
__global__ __launch_bounds__(256) void gemm_ATxW(const float* __restrict__ A,
                                                 const float* __restrict__ W,
                                                 const float* __restrict__ bias,
                                                 float* __restrict__ out) {
    int b  = blockIdx.z;
    int n0 = blockIdx.x * 64;
    int c0 = blockIdx.y * 64;
    __shared__ float As[16][64];
    __shared__ float Bs[16][64];
    int tid = threadIdx.x;
    int tc = tid & 15, tn = tid >> 4;
    int lr = tid >> 4;          // load row (k)
    int lm = (tid & 15) * 4;    // load col
    const float* Ab = A + (size_t)b * CDIM * NPIX;
    float acc[4][4] = {};
    for (int k0 = 0; k0 < CDIM; k0 += 16) {
        *(float4*)&As[lr][lm] = *(const float4*)&Ab[(size_t)(k0 + lr) * NPIX + n0 + lm];
        *(float4*)&Bs[lr][lm] = *(const float4*)&W[(size_t)(k0 + lr) * CDIM + c0 + lm];
        __syncthreads();
        #pragma unroll
        for (int kk = 0; kk < 16; kk++) {
            float4 a  = *(const float4*)&As[kk][tn * 4];
            float4 bb = *(const float4*)&Bs[kk][tc * 4];
            float av[4] = {a.x, a.y, a.z, a.w};
            float bv[4] = {bb.x, bb.y, bb.z, bb.w};
            #pragma unroll
            for (int i = 0; i < 4; i++)
                #pragma unroll
                for (int j = 0; j < 4; j++)
                    acc[i][j] += av[i] * bv[j];
        }
        __syncthreads();
    }
    float4 b4 = *(const float4*)&bias[c0 + tc * 4];
    float bvv[4] = {b4.x, b4.y, b4.z, b4.w};
    float* Ob = out + ((size_t)b * NPIX + n0 + tn * 4) * CDIM + c0 + tc * 4;
    #pragma unroll
    for (int i = 0; i < 4; i++) {
        float4 r = {acc[i][0] + bvv[0], acc[i][1] + bvv[1],
                    acc[i][2] + bvv[2], acc[i][3] + bvv[3]};
        *(float4*)&Ob[(size_t)i * CDIM] = r;
    }
}

// ---------------- fused block sparse attention ----------------
// 16 consecutive queries (one q_low block) share the 32 gathered keys.
// CTA = (q_low, b); 128 threads = 16 queries x 8 heads.
// dynamic smem: Ks[32][256], Vs[32][256] = 64 KB
__global__ __launch_bounds__(128) void attn_kernel(const float* __restrict__ qproj,
                                                   const float* __restrict__ kproj,
                                                   const float* __restrict__ vproj,
                                                   const int* __restrict__ idx,
                                                   float* __restrict__ x) {
    int qlow = blockIdx.x;
    int b    = blockIdx.y;
    extern __shared__ float sm[];
    float* Ks = sm;                // [32][256]
    float* Vs = sm + KLEN * CDIM;  // [32][256]
    __shared__ int sidx[KLEN];
    int t = threadIdx.x;
    if (t < KLEN) sidx[t] = idx[((size_t)b * NLOW + qlow) * KLEN + t];
    __syncthreads();

    // cooperative gather of K/V rows into smem (float4, coalesced)
    const float4* kp4 = (const float4*)kproj;
    const float4* vp4 = (const float4*)vproj;
    float4* Ks4 = (float4*)Ks;
    float4* Vs4 = (float4*)Vs;
    #pragma unroll
    for (int c = 0; c < 16; c++) {
        int li = c * 128 + t;              // 0..2047
        int r  = li >> 6;                  // key row 0..31
        int c4 = li & 63;                  // float4 col 0..63
        size_t src = ((size_t)(b * NPIX + sidx[r])) * 64 + c4;
        Ks4[li] = kp4[src];
        Vs4[li] = vp4[src];
    }
    __syncthreads();

    int h = t >> 4;          // head 0..7
    int q = t & 15;          // query-in-block 0..15
    int n = qlow * 16 + q;

    float qreg[HD];
    const float4* qp4 = (const float4*)(qproj + ((size_t)(b * NPIX + n)) * CDIM + h * HD);
    #pragma unroll
    for (int d4 = 0; d4 < 8; d4++) {
        float4 v = qp4[d4];
        qreg[d4 * 4 + 0] = v.x; qreg[d4 * 4 + 1] = v.y;
        qreg[d4 * 4 + 2] = v.z; qreg[d4 * 4 + 3] = v.w;
    }

    const float scale = 0.17677669529663687f;  // 32^-0.5
    float s[KLEN];
    #pragma unroll
    for (int k = 0; k < KLEN; k++) {
        const float4* kr = (const float4*)(Ks + k * CDIM + h * HD);
        float acc = 0.f;
        #pragma unroll
        for (int d4 = 0; d4 < 8; d4++) {
            float4 kv = kr[d4];
            acc += qreg[d4 * 4 + 0] * kv.x + qreg[d4 * 4 + 1] * kv.y
                 + qreg[d4 * 4 + 2] * kv.z + qreg[d4 * 4 + 3] * kv.w;
        }
        s[k] = acc * scale;
    }

    float m = s[0];
    #pragma unroll
    for (int k = 1; k < KLEN; k++) m = fmaxf(m, s[k]);
    float sum = 0.f;
    #pragma unroll
    for (int k = 0; k < KLEN; k++) { s[k] = expf(s[k] - m); sum += s[k]; }

    float o[HD] = {};
    #pragma unroll
    for (int k = 0; k < KLEN; k++) {
        float p = s[k];
        const float4* vr = (const float4*)(Vs + k * CDIM + h * HD);
        #pragma unroll
        for (int d4 = 0; d4 < 8; d4++) {
            float4 vv = vr[d4];
            o[d4 * 4 + 0] += p * vv.x; o[d4 * 4 + 1] += p * vv.y;
            o[d4 * 4 + 2] += p * vv.z; o[d4 * 4 + 3] += p * vv.w;
        }
    }
    float inv = 1.f / sum;
    float4* xo = (float4*)(x + ((size_t)(b * NPIX + n)) * CDIM + h * HD);
    #pragma unroll
    for (int d4 = 0; d4 < 8; d4++) {
        float4 r = {o[d4 * 4 + 0] * inv, o[d4 * 4 + 1] * inv,
                    o[d4 * 4 + 2] * inv, o[d4 * 4 + 3] * inv};
        xo[d4] = r;
    }
}

// ---------------- output GEMM: out[b,co,n] = sum_c X[b,n,c]*Wo[c,co]+bo ----------------
// X is (B, NPIX, C) (c contiguous), out is (B, C, NPIX) (n contiguous)
__global__ __launch_bounds__(256) void gemm_xWo(const float* __restrict__ X,
                                                const float* __restrict__ W,
                                                const float* __restrict__ bias,
                                                float* __restrict__ out) {
    int b  = blockIdx.z;
    int n0 = blockIdx.x * 64;
    int c0 = blockIdx.y * 64;
    __shared__ float As[16][68];   // padded (68*4B=272B, 16B-aligned rows)
    __shared__ float Bs[16][64];
    int tid = threadIdx.x;
    int tn = tid & 15, tc = tid >> 4;
    const float* Xb = X + (size_t)b * NPIX * CDIM;
    float acc[4][4] = {};          // [co j][n i]
    int lm = tid >> 2;             // n row 0..63
    int lk = (tid & 3) * 4;        // k offset 0,4,8,12
    int lr = tid >> 4;             // Bs row
    int lc = (tid & 15) * 4;
    for (int k0 = 0; k0 < CDIM; k0 += 16) {
        float4 v = *(const float4*)&Xb[(size_t)(n0 + lm) * CDIM + k0 + lk];
        As[lk + 0][lm] = v.x; As[lk + 1][lm] = v.y;
        As[lk + 2][lm] = v.z; As[lk + 3][lm] = v.w;
        *(float4*)&Bs[lr][lc] = *(const float4*)&W[(size_t)(k0 + lr) * CDIM + c0 + lc];
        __syncthreads();
        #pragma unroll
        for (int kk = 0; kk < 16; kk++) {
            float4 a  = *(const float4*)&As[kk][tn * 4];
            float4 bb = *(const float4*)&Bs[kk][tc * 4];
            float av[4] = {a.x, a.y, a.z, a.w};
            float bv[4] = {bb.x, bb.y, bb.z, bb.w};
            #pragma unroll
            for (int j = 0; j < 4; j++)
                #pragma unroll
                for (int i = 0; i < 4; i++)
                    acc[j][i] += bv[j] * av[i];
        }
        __syncthreads();
    }
    float* Ob = out + (size_t)b * CDIM * NPIX + (size_t)(c0 + tc * 4) * NPIX + n0 + tn * 4;
    #pragma unroll
    for (int j = 0; j < 4; j++) {
        float bb = bias[c0 + tc * 4 + j];
        float4 r = {acc[j][0] + bb, acc[j][1] + bb, acc[j][2] + bb, acc[j][3] + bb};
        *(float4*)&Ob[(size_t)j * NPIX] = r;
    }
}

// ---------------- launch ----------------
extern "C" void kernel_launch(void* const* d_in, const int* in_sizes, int n_in,
                              void* d_out, int out_size) {
    const float* qh   = (const float*)d_in[0];
    const float* kh   = (const float*)d_in[1];
    const float* vh   = (const float*)d_in[2];
    const float* cmap = (const float*)d_in[3];
    const float* Wq   = (const float*)d_in[4];
    const float* bq   = (const float*)d_in[5];
    const float* Wk   = (const float*)d_in[6];
    const float* bk   = (const float*)d_in[7];
    const float* Wv   = (const float*)d_in[8];
    const float* bv   = (const float*)d_in[9];
    const float* Wo   = (const float*)d_in[10];
    const float* bo   = (const float*)d_in[11];
    float* out = (float*)d_out;

    float *pq, *pk, *pv, *px;
    int* pidx;
    cudaGetSymbolAddress((void**)&pq,   g_q);
    cudaGetSymbolAddress((void**)&pk,   g_k);
    cudaGetSymbolAddress((void**)&pv,   g_v);
    cudaGetSymbolAddress((void**)&px,   g_x);
    cudaGetSymbolAddress((void**)&pidx, g_idx);

    cudaFuncSetAttribute(attn_kernel, cudaFuncAttributeMaxDynamicSharedMemorySize, 65536);

    topk_expand_kernel<<<BATCH, NLOW>>>(cmap, pidx);

    dim3 gg(NPIX / 64, CDIM / 64, BATCH);
    gemm_ATxW<<<gg, 256>>>(qh, Wq, bq, pq);
    gemm_ATxW<<<gg, 256>>>(kh, Wk, bk, pk);
    gemm_ATxW<<<gg, 256>>>(vh, Wv, bv, pv);

    attn_kernel<<<dim3(NLOW, BATCH), 128, 65536>>>(pq, pk, pv, pidx, px);

    gemm_xWo<<<gg, 256>>>(px, Wo, bo, out);
}